// round 4
// baseline (speedup 1.0000x reference)
#include <cuda_runtime.h>
#include <cuda_fp16.h>
#include <stdint.h>

#define N_NODES 50000
#define D_FEAT  128

// fp16 copy of h, rebuilt every kernel_launch (graph-safe, no allocation).
__device__ __half2 g_h16[N_NODES * (D_FEAT / 2)];

// 1 if indices are int64, 0 if int32. Written by convert_kernel block 0.
__device__ int g_idx_is64;

// Convert h (fp32) -> g_h16 (fp16). Block 0 additionally detects the index
// dtype: for int64 indices (values < 50000) every odd 32-bit word is zero;
// for int32 the OR over 2048 odd words is nonzero with overwhelming
// probability. Runs concurrently with the conversion, so its DRAM latency
// is hidden behind the other blocks.
__global__ __launch_bounds__(256) void convert_kernel(
    const float4* __restrict__ h4, int n4,
    const unsigned* __restrict__ src_words)
{
    if (blockIdx.x == 0) {
        __shared__ unsigned red[256];
        unsigned v = 0;
        #pragma unroll 4
        for (int i = threadIdx.x; i < 2048; i += 256)
            v |= __ldcs(&src_words[2 * i + 1]);
        red[threadIdx.x] = v;
        __syncthreads();
        for (int s = 128; s > 0; s >>= 1) {
            if (threadIdx.x < s) red[threadIdx.x] |= red[threadIdx.x + s];
            __syncthreads();
        }
        if (threadIdx.x == 0) g_idx_is64 = (red[0] == 0u) ? 1 : 0;
    }

    int i = blockIdx.x * blockDim.x + threadIdx.x;
    if (i >= n4) return;
    float4 v = __ldcs(&h4[i]);
    __half2 lo = __floats2half2_rn(v.x, v.y);
    __half2 hi = __floats2half2_rn(v.z, v.w);
    ((__half2*)g_h16)[2 * i]     = lo;
    ((__half2*)g_h16)[2 * i + 1] = hi;
}

// 4 lanes per edge. Row = 128 halves = 256B = 16 uint4. Lane g loads uint4
// indices {g, g+4, g+8, g+12} from each row: 8 independent LDG.128 per
// thread issued up-front. fp32 accumulation, 2-step shfl group reduction.
__global__ __launch_bounds__(256) void edge_dot_kernel(
    const void* __restrict__ srcp,
    const void* __restrict__ dstp,
    float*      __restrict__ out,
    int E)
{
    const int gtid = blockIdx.x * blockDim.x + threadIdx.x;
    const int edge = gtid >> 2;
    const int g    = threadIdx.x & 3;
    if (edge >= E) return;

    long long s, d;
    if (g_idx_is64) {
        s = __ldcs(&((const long long*)srcp)[edge]);
        d = __ldcs(&((const long long*)dstp)[edge]);
    } else {
        s = (long long)__ldcs(&((const int*)srcp)[edge]);
        d = (long long)__ldcs(&((const int*)dstp)[edge]);
    }

    const uint4* __restrict__ ra = (const uint4*)(g_h16 + s * (D_FEAT / 2)) + g;
    const uint4* __restrict__ rb = (const uint4*)(g_h16 + d * (D_FEAT / 2)) + g;

    uint4 a0 = __ldg(ra + 0);
    uint4 a1 = __ldg(ra + 4);
    uint4 a2 = __ldg(ra + 8);
    uint4 a3 = __ldg(ra + 12);
    uint4 b0 = __ldg(rb + 0);
    uint4 b1 = __ldg(rb + 4);
    uint4 b2 = __ldg(rb + 8);
    uint4 b3 = __ldg(rb + 12);

    float acc0 = 0.f, acc1 = 0.f, acc2 = 0.f, acc3 = 0.f;

    #define DOT_U4(A, B, ACC)                                            \
    {                                                                    \
        float2 fa, fb;                                                   \
        fa = __half22float2(*(const __half2*)&(A).x);                    \
        fb = __half22float2(*(const __half2*)&(B).x);                    \
        ACC = fmaf(fa.x, fb.x, ACC); ACC = fmaf(fa.y, fb.y, ACC);        \
        fa = __half22float2(*(const __half2*)&(A).y);                    \
        fb = __half22float2(*(const __half2*)&(B).y);                    \
        ACC = fmaf(fa.x, fb.x, ACC); ACC = fmaf(fa.y, fb.y, ACC);        \
        fa = __half22float2(*(const __half2*)&(A).z);                    \
        fb = __half22float2(*(const __half2*)&(B).z);                    \
        ACC = fmaf(fa.x, fb.x, ACC); ACC = fmaf(fa.y, fb.y, ACC);        \
        fa = __half22float2(*(const __half2*)&(A).w);                    \
        fb = __half22float2(*(const __half2*)&(B).w);                    \
        ACC = fmaf(fa.x, fb.x, ACC); ACC = fmaf(fa.y, fb.y, ACC);        \
    }

    DOT_U4(a0, b0, acc0)
    DOT_U4(a1, b1, acc1)
    DOT_U4(a2, b2, acc2)
    DOT_U4(a3, b3, acc3)

    float p = (acc0 + acc1) + (acc2 + acc3);

    p += __shfl_xor_sync(0xffffffffu, p, 2);
    p += __shfl_xor_sync(0xffffffffu, p, 1);

    if (g == 0) __stcs(&out[edge], p);
}

extern "C" void kernel_launch(void* const* d_in, const int* in_sizes, int n_in,
                              void* d_out, int out_size) {
    const float* h   = (const float*)d_in[0];
    const void*  src = d_in[1];
    const void*  dst = d_in[2];
    float*       out = (float*)d_out;
    const int E  = in_sizes[1];
    const int n4 = in_sizes[0] / 4;   // N*D/4 float4s

    convert_kernel<<<(n4 + 255) / 256, 256>>>(
        (const float4*)h, n4, (const unsigned*)src);

    const int threads = 256;
    const long long total = (long long)E * 4;
    const int blocks = (int)((total + threads - 1) / threads);
    edge_dot_kernel<<<blocks, threads>>>(src, dst, out, E);
}

// round 6
// speedup vs baseline: 1.0592x; 1.0592x over previous
#include <cuda_runtime.h>
#include <cuda_fp16.h>
#include <stdint.h>

#define N_NODES 50000
#define D_FEAT  128

// fp16 copy of h, rebuilt every kernel_launch (graph-safe, no allocation).
__device__ __half2 g_h16[N_NODES * (D_FEAT / 2)];

// 1 if indices are int64, 0 if int32. Written by convert_kernel block 0.
__device__ int g_idx_is64;

// Convert h (fp32) -> g_h16 (fp16). Block 0 additionally detects the index
// dtype (int64 indices < 50000 have all-zero odd words; int32 does not).
__global__ __launch_bounds__(256) void convert_kernel(
    const float4* __restrict__ h4, int n4,
    const unsigned* __restrict__ src_words)
{
    if (blockIdx.x == 0) {
        __shared__ unsigned red[256];
        unsigned v = 0;
        #pragma unroll 4
        for (int i = threadIdx.x; i < 2048; i += 256)
            v |= __ldcs(&src_words[2 * i + 1]);
        red[threadIdx.x] = v;
        __syncthreads();
        for (int s = 128; s > 0; s >>= 1) {
            if (threadIdx.x < s) red[threadIdx.x] |= red[threadIdx.x + s];
            __syncthreads();
        }
        if (threadIdx.x == 0) g_idx_is64 = (red[0] == 0u) ? 1 : 0;
    }

    int i = blockIdx.x * blockDim.x + threadIdx.x;
    if (i >= n4) return;
    float4 v = __ldcs(&h4[i]);
    __half2 lo = __floats2half2_rn(v.x, v.y);
    __half2 hi = __floats2half2_rn(v.z, v.w);
    ((__half2*)g_h16)[2 * i]     = lo;
    ((__half2*)g_h16)[2 * i + 1] = hi;
}

// 8 lanes per edge. Row = 128 halves = 256B = 16 uint4. Lane g loads uint4
// {g, g+8} from each row, so every LDG.128 step has each aligned 8-lane
// group reading one FULL contiguous 128B line -> 100% useful bytes per L1
// wavefront (the 4-lane shape only delivered 64B/line). 4 independent loads
// per thread, fp32 accumulation, 3-step shfl group reduction.
__global__ __launch_bounds__(256) void edge_dot_kernel(
    const void* __restrict__ srcp,
    const void* __restrict__ dstp,
    float*      __restrict__ out,
    int E)
{
    const int gtid = blockIdx.x * blockDim.x + threadIdx.x;
    const int edge = gtid >> 3;
    const int g    = threadIdx.x & 7;
    if (edge >= E) return;

    long long s, d;
    if (g_idx_is64) {
        s = __ldcs(&((const long long*)srcp)[edge]);
        d = __ldcs(&((const long long*)dstp)[edge]);
    } else {
        s = (long long)__ldcs(&((const int*)srcp)[edge]);
        d = (long long)__ldcs(&((const int*)dstp)[edge]);
    }

    const uint4* __restrict__ ra = (const uint4*)(g_h16 + s * (D_FEAT / 2)) + g;
    const uint4* __restrict__ rb = (const uint4*)(g_h16 + d * (D_FEAT / 2)) + g;

    uint4 a0 = __ldg(ra + 0);
    uint4 a1 = __ldg(ra + 8);
    uint4 b0 = __ldg(rb + 0);
    uint4 b1 = __ldg(rb + 8);

    float acc0 = 0.f, acc1 = 0.f;

    #define DOT_U4(A, B, ACC)                                            \
    {                                                                    \
        float2 fa, fb;                                                   \
        fa = __half22float2(*(const __half2*)&(A).x);                    \
        fb = __half22float2(*(const __half2*)&(B).x);                    \
        ACC = fmaf(fa.x, fb.x, ACC); ACC = fmaf(fa.y, fb.y, ACC);        \
        fa = __half22float2(*(const __half2*)&(A).y);                    \
        fb = __half22float2(*(const __half2*)&(B).y);                    \
        ACC = fmaf(fa.x, fb.x, ACC); ACC = fmaf(fa.y, fb.y, ACC);        \
        fa = __half22float2(*(const __half2*)&(A).z);                    \
        fb = __half22float2(*(const __half2*)&(B).z);                    \
        ACC = fmaf(fa.x, fb.x, ACC); ACC = fmaf(fa.y, fb.y, ACC);        \
        fa = __half22float2(*(const __half2*)&(A).w);                    \
        fb = __half22float2(*(const __half2*)&(B).w);                    \
        ACC = fmaf(fa.x, fb.x, ACC); ACC = fmaf(fa.y, fb.y, ACC);        \
    }

    DOT_U4(a0, b0, acc0)
    DOT_U4(a1, b1, acc1)

    float p = acc0 + acc1;

    p += __shfl_xor_sync(0xffffffffu, p, 4);
    p += __shfl_xor_sync(0xffffffffu, p, 2);
    p += __shfl_xor_sync(0xffffffffu, p, 1);

    if (g == 0) __stcs(&out[edge], p);
}

extern "C" void kernel_launch(void* const* d_in, const int* in_sizes, int n_in,
                              void* d_out, int out_size) {
    const float* h   = (const float*)d_in[0];
    const void*  src = d_in[1];
    const void*  dst = d_in[2];
    float*       out = (float*)d_out;
    const int E  = in_sizes[1];
    const int n4 = in_sizes[0] / 4;   // N*D/4 float4s

    convert_kernel<<<(n4 + 255) / 256, 256>>>(
        (const float4*)h, n4, (const unsigned*)src);

    const int threads = 256;
    const long long total = (long long)E * 8;
    const int blocks = (int)((total + threads - 1) / threads);
    edge_dot_kernel<<<blocks, threads>>>(src, dst, out, E);
}

// round 7
// speedup vs baseline: 1.1341x; 1.0707x over previous
#include <cuda_runtime.h>
#include <cuda_fp16.h>
#include <stdint.h>

#define N_NODES 50000
#define D_FEAT  128

// fp16 copy of h, rebuilt every kernel_launch (graph-safe, no allocation).
__device__ __half2 g_h16[N_NODES * (D_FEAT / 2)];

// 1 if indices are int64, 0 if int32. Written by convert_kernel block 0.
__device__ int g_idx_is64;

// Convert h (fp32) -> g_h16 (fp16). Block 0 additionally detects the index
// dtype (int64 indices < 50000 have all-zero odd words; int32 does not).
__global__ __launch_bounds__(256) void convert_kernel(
    const float4* __restrict__ h4, int n4,
    const unsigned* __restrict__ src_words)
{
    if (blockIdx.x == 0) {
        __shared__ unsigned red[256];
        unsigned v = 0;
        #pragma unroll 4
        for (int i = threadIdx.x; i < 2048; i += 256)
            v |= __ldcs(&src_words[2 * i + 1]);
        red[threadIdx.x] = v;
        __syncthreads();
        for (int s = 128; s > 0; s >>= 1) {
            if (threadIdx.x < s) red[threadIdx.x] |= red[threadIdx.x + s];
            __syncthreads();
        }
        if (threadIdx.x == 0) g_idx_is64 = (red[0] == 0u) ? 1 : 0;
    }

    int i = blockIdx.x * blockDim.x + threadIdx.x;
    if (i >= n4) return;
    float4 v = __ldcs(&h4[i]);
    __half2 lo = __floats2half2_rn(v.x, v.y);
    __half2 hi = __floats2half2_rn(v.z, v.w);
    ((__half2*)g_h16)[2 * i]     = lo;
    ((__half2*)g_h16)[2 * i + 1] = hi;
}

// 8 lanes per group, TWO edges per group. Row = 256B = 16 uint4; lane g
// loads uint4 {g, g+8} from each of 4 rows (2 edges x {src,dst}) -> 8
// independent LDG.128 per thread, every one a full contiguous 128B line per
// aligned 8-lane group. fp32 accumulation; combined 4-shfl reduction for
// both edges (p0 routed to lanes 0-3, p1 to lanes 4-7 after the xor-4 step).
__global__ __launch_bounds__(256) void edge_dot_kernel(
    const void* __restrict__ srcp,
    const void* __restrict__ dstp,
    float*      __restrict__ out,
    int E)
{
    const int gtid = blockIdx.x * blockDim.x + threadIdx.x;
    const int grp  = gtid >> 3;          // group id
    const int g    = threadIdx.x & 7;    // lane within group
    const int e0   = grp * 2;
    const int e1   = e0 + 1;
    if (e0 >= E) return;
    const bool has1 = (e1 < E);

    long long s0, d0, s1, d1;
    if (g_idx_is64) {
        const long long* sp = (const long long*)srcp;
        const long long* dp = (const long long*)dstp;
        s0 = __ldcs(&sp[e0]); d0 = __ldcs(&dp[e0]);
        s1 = has1 ? __ldcs(&sp[e1]) : s0;
        d1 = has1 ? __ldcs(&dp[e1]) : d0;
    } else {
        const int* sp = (const int*)srcp;
        const int* dp = (const int*)dstp;
        s0 = (long long)__ldcs(&sp[e0]); d0 = (long long)__ldcs(&dp[e0]);
        s1 = has1 ? (long long)__ldcs(&sp[e1]) : s0;
        d1 = has1 ? (long long)__ldcs(&dp[e1]) : d0;
    }

    const uint4* __restrict__ ra0 = (const uint4*)(g_h16 + s0 * (D_FEAT / 2)) + g;
    const uint4* __restrict__ rb0 = (const uint4*)(g_h16 + d0 * (D_FEAT / 2)) + g;
    const uint4* __restrict__ ra1 = (const uint4*)(g_h16 + s1 * (D_FEAT / 2)) + g;
    const uint4* __restrict__ rb1 = (const uint4*)(g_h16 + d1 * (D_FEAT / 2)) + g;

    // 8 independent loads, all issued before any consumption.
    uint4 a00 = __ldg(ra0 + 0);
    uint4 a01 = __ldg(ra0 + 8);
    uint4 b00 = __ldg(rb0 + 0);
    uint4 b01 = __ldg(rb0 + 8);
    uint4 a10 = __ldg(ra1 + 0);
    uint4 a11 = __ldg(ra1 + 8);
    uint4 b10 = __ldg(rb1 + 0);
    uint4 b11 = __ldg(rb1 + 8);

    #define DOT_U4(A, B, ACC)                                            \
    {                                                                    \
        float2 fa, fb;                                                   \
        fa = __half22float2(*(const __half2*)&(A).x);                    \
        fb = __half22float2(*(const __half2*)&(B).x);                    \
        ACC = fmaf(fa.x, fb.x, ACC); ACC = fmaf(fa.y, fb.y, ACC);        \
        fa = __half22float2(*(const __half2*)&(A).y);                    \
        fb = __half22float2(*(const __half2*)&(B).y);                    \
        ACC = fmaf(fa.x, fb.x, ACC); ACC = fmaf(fa.y, fb.y, ACC);        \
        fa = __half22float2(*(const __half2*)&(A).z);                    \
        fb = __half22float2(*(const __half2*)&(B).z);                    \
        ACC = fmaf(fa.x, fb.x, ACC); ACC = fmaf(fa.y, fb.y, ACC);        \
        fa = __half22float2(*(const __half2*)&(A).w);                    \
        fb = __half22float2(*(const __half2*)&(B).w);                    \
        ACC = fmaf(fa.x, fb.x, ACC); ACC = fmaf(fa.y, fb.y, ACC);        \
    }

    float p0a = 0.f, p0b = 0.f, p1a = 0.f, p1b = 0.f;
    DOT_U4(a00, b00, p0a)
    DOT_U4(a01, b01, p0b)
    DOT_U4(a10, b10, p1a)
    DOT_U4(a11, b11, p1b)
    float p0 = p0a + p0b;
    float p1 = p1a + p1b;

    // Combined reduction: xor-4 on both edges, then route p0 -> lanes 0-3,
    // p1 -> lanes 4-7, and finish both with two more shfl steps.
    p0 += __shfl_xor_sync(0xffffffffu, p0, 4);
    p1 += __shfl_xor_sync(0xffffffffu, p1, 4);
    float v = (g < 4) ? p0 : p1;
    v += __shfl_xor_sync(0xffffffffu, v, 2);
    v += __shfl_xor_sync(0xffffffffu, v, 1);

    if (g == 0) __stcs(&out[e0], v);
    if (g == 4 && has1) __stcs(&out[e1], v);
}

extern "C" void kernel_launch(void* const* d_in, const int* in_sizes, int n_in,
                              void* d_out, int out_size) {
    const float* h   = (const float*)d_in[0];
    const void*  src = d_in[1];
    const void*  dst = d_in[2];
    float*       out = (float*)d_out;
    const int E  = in_sizes[1];
    const int n4 = in_sizes[0] / 4;   // N*D/4 float4s

    convert_kernel<<<(n4 + 255) / 256, 256>>>(
        (const float4*)h, n4, (const unsigned*)src);

    const int threads = 256;
    const int npairs  = (E + 1) / 2;                 // groups of 2 edges
    const long long total = (long long)npairs * 8;   // 8 lanes per group
    const int blocks = (int)((total + threads - 1) / threads);
    edge_dot_kernel<<<blocks, threads>>>(src, dst, out, E);
}

// round 9
// speedup vs baseline: 1.2176x; 1.0737x over previous
#include <cuda_runtime.h>
#include <cuda_fp16.h>
#include <stdint.h>

#define N_NODES 50000
#define D_FEAT  128

// fp16 copy of h, rebuilt every kernel_launch (graph-safe, no allocation).
__device__ __half2 g_h16[N_NODES * (D_FEAT / 2)];

// 1 if indices are int64, 0 if int32. Written by convert_kernel block 0.
__device__ int g_idx_is64;

// Convert h (fp32) -> g_h16 (fp16). Block 0 additionally detects the index
// dtype (int64 indices < 50000 have all-zero odd words; int32 does not).
__global__ __launch_bounds__(256) void convert_kernel(
    const float4* __restrict__ h4, int n4,
    const unsigned* __restrict__ src_words)
{
    if (blockIdx.x == 0) {
        __shared__ unsigned red[256];
        unsigned v = 0;
        #pragma unroll 4
        for (int i = threadIdx.x; i < 2048; i += 256)
            v |= __ldcs(&src_words[2 * i + 1]);
        red[threadIdx.x] = v;
        __syncthreads();
        for (int s = 128; s > 0; s >>= 1) {
            if (threadIdx.x < s) red[threadIdx.x] |= red[threadIdx.x + s];
            __syncthreads();
        }
        if (threadIdx.x == 0) g_idx_is64 = (red[0] == 0u) ? 1 : 0;
    }

    int i = blockIdx.x * blockDim.x + threadIdx.x;
    if (i >= n4) return;
    float4 v = __ldcs(&h4[i]);
    __half2 lo = __floats2half2_rn(v.x, v.y);
    __half2 hi = __floats2half2_rn(v.z, v.w);
    ((__half2*)g_h16)[2 * i]     = lo;
    ((__half2*)g_h16)[2 * i + 1] = hi;
}

// 8 lanes per group, TWO edges per group, full-128B-line LDG.128 accesses.
// Math per uint4 pair uses fp16 products + ONE level of fp16 pairwise add,
// then converts 2-term sums to fp32 and accumulates: 14 instrs per 16
// elements vs 24 for the all-fp32 ladder.
__global__ __launch_bounds__(256) void edge_dot_kernel(
    const void* __restrict__ srcp,
    const void* __restrict__ dstp,
    float*      __restrict__ out,
    int E)
{
    const int gtid = blockIdx.x * blockDim.x + threadIdx.x;
    const int grp  = gtid >> 3;          // group id
    const int g    = threadIdx.x & 7;    // lane within group
    const int e0   = grp * 2;
    const int e1   = e0 + 1;
    if (e0 >= E) return;
    const bool has1 = (e1 < E);

    long long s0, d0, s1, d1;
    if (g_idx_is64) {
        const long long* sp = (const long long*)srcp;
        const long long* dp = (const long long*)dstp;
        s0 = __ldcs(&sp[e0]); d0 = __ldcs(&dp[e0]);
        s1 = has1 ? __ldcs(&sp[e1]) : s0;
        d1 = has1 ? __ldcs(&dp[e1]) : d0;
    } else {
        const int* sp = (const int*)srcp;
        const int* dp = (const int*)dstp;
        s0 = (long long)__ldcs(&sp[e0]); d0 = (long long)__ldcs(&dp[e0]);
        s1 = has1 ? (long long)__ldcs(&sp[e1]) : s0;
        d1 = has1 ? (long long)__ldcs(&dp[e1]) : d0;
    }

    const uint4* __restrict__ ra0 = (const uint4*)(g_h16 + s0 * (D_FEAT / 2)) + g;
    const uint4* __restrict__ rb0 = (const uint4*)(g_h16 + d0 * (D_FEAT / 2)) + g;
    const uint4* __restrict__ ra1 = (const uint4*)(g_h16 + s1 * (D_FEAT / 2)) + g;
    const uint4* __restrict__ rb1 = (const uint4*)(g_h16 + d1 * (D_FEAT / 2)) + g;

    // 8 independent loads, all issued before any consumption.
    uint4 a00 = __ldg(ra0 + 0);
    uint4 a01 = __ldg(ra0 + 8);
    uint4 b00 = __ldg(rb0 + 0);
    uint4 b01 = __ldg(rb0 + 8);
    uint4 a10 = __ldg(ra1 + 0);
    uint4 a11 = __ldg(ra1 + 8);
    uint4 b10 = __ldg(rb1 + 0);
    uint4 b11 = __ldg(rb1 + 8);

    // fp16 products, one pairwise fp16 add, then fp32 accumulation.
    // Macro locals are underscore-prefixed so ACC (outer float) never
    // collides with them.
    #define DOT_U4(A, B, ACC)                                              \
    {                                                                      \
        __half2 _dp0 = __hmul2(*(const __half2*)&(A).x,                    \
                               *(const __half2*)&(B).x);                   \
        __half2 _dp1 = __hmul2(*(const __half2*)&(A).y,                    \
                               *(const __half2*)&(B).y);                   \
        __half2 _dp2 = __hmul2(*(const __half2*)&(A).z,                    \
                               *(const __half2*)&(B).z);                   \
        __half2 _dp3 = __hmul2(*(const __half2*)&(A).w,                    \
                               *(const __half2*)&(B).w);                   \
        __half2 _dq0 = __hadd2(_dp0, _dp1);                                \
        __half2 _dq1 = __hadd2(_dp2, _dp3);                                \
        float2 _df0 = __half22float2(_dq0);                                \
        float2 _df1 = __half22float2(_dq1);                                \
        ACC += (_df0.x + _df0.y) + (_df1.x + _df1.y);                      \
    }

    float p0 = 0.f, p1 = 0.f;
    DOT_U4(a00, b00, p0)
    DOT_U4(a01, b01, p0)
    DOT_U4(a10, b10, p1)
    DOT_U4(a11, b11, p1)

    // Combined reduction: xor-4 on both edges, then route p0 -> lanes 0-3,
    // p1 -> lanes 4-7, and finish both with two more shfl steps.
    p0 += __shfl_xor_sync(0xffffffffu, p0, 4);
    p1 += __shfl_xor_sync(0xffffffffu, p1, 4);
    float v = (g < 4) ? p0 : p1;
    v += __shfl_xor_sync(0xffffffffu, v, 2);
    v += __shfl_xor_sync(0xffffffffu, v, 1);

    if (g == 0) __stcs(&out[e0], v);
    if (g == 4 && has1) __stcs(&out[e1], v);
}

extern "C" void kernel_launch(void* const* d_in, const int* in_sizes, int n_in,
                              void* d_out, int out_size) {
    const float* h   = (const float*)d_in[0];
    const void*  src = d_in[1];
    const void*  dst = d_in[2];
    float*       out = (float*)d_out;
    const int E  = in_sizes[1];
    const int n4 = in_sizes[0] / 4;   // N*D/4 float4s

    convert_kernel<<<(n4 + 255) / 256, 256>>>(
        (const float4*)h, n4, (const unsigned*)src);

    const int threads = 256;
    const int npairs  = (E + 1) / 2;                 // groups of 2 edges
    const long long total = (long long)npairs * 8;   // 8 lanes per group
    const int blocks = (int)((total + threads - 1) / threads);
    edge_dot_kernel<<<blocks, threads>>>(src, dst, out, E);
}

// round 11
// speedup vs baseline: 1.2942x; 1.0629x over previous
#include <cuda_runtime.h>
#include <cuda_fp16.h>
#include <stdint.h>

#define N_NODES 50000
#define D_FEAT  128

// fp16 copy of h, rebuilt every kernel_launch (graph-safe, no allocation).
__device__ __half2 g_h16[N_NODES * (D_FEAT / 2)];

// 1 if indices are int64, 0 if int32. Written by convert_kernel block 0.
__device__ int g_idx_is64;

// Convert h (fp32) -> g_h16 (fp16). Block 0 additionally detects the index
// dtype (int64 indices < 50000 have all-zero odd words; int32 does not).
__global__ __launch_bounds__(256) void convert_kernel(
    const float4* __restrict__ h4, int n4,
    const unsigned* __restrict__ src_words)
{
    if (blockIdx.x == 0) {
        __shared__ unsigned red[256];
        unsigned v = 0;
        #pragma unroll 4
        for (int i = threadIdx.x; i < 2048; i += 256)
            v |= __ldcs(&src_words[2 * i + 1]);
        red[threadIdx.x] = v;
        __syncthreads();
        for (int s = 128; s > 0; s >>= 1) {
            if (threadIdx.x < s) red[threadIdx.x] |= red[threadIdx.x + s];
            __syncthreads();
        }
        if (threadIdx.x == 0) g_idx_is64 = (red[0] == 0u) ? 1 : 0;
    }

    int i = blockIdx.x * blockDim.x + threadIdx.x;
    if (i >= n4) return;
    float4 v = __ldcs(&h4[i]);
    __half2 lo = __floats2half2_rn(v.x, v.y);
    __half2 hi = __floats2half2_rn(v.z, v.w);
    ((__half2*)g_h16)[2 * i]     = lo;
    ((__half2*)g_h16)[2 * i + 1] = hi;
}

// 8 lanes per group, TWO edges per group, full-128B-line LDG.128 accesses,
// fp16 product + depth-1 fp16 add math, fp32 carry. This round: 32-bit
// uint4-offset addressing (row offset = idx*16, max 800k) and
// __launch_bounds__(256, 8) to cap regs at 32 -> full 64-warp residency.
__global__ __launch_bounds__(256, 8) void edge_dot_kernel(
    const void* __restrict__ srcp,
    const void* __restrict__ dstp,
    float*      __restrict__ out,
    int E)
{
    const int gtid = blockIdx.x * blockDim.x + threadIdx.x;
    const int grp  = gtid >> 3;          // group id
    const int g    = threadIdx.x & 7;    // lane within group
    const int e0   = grp * 2;
    const int e1   = e0 + 1;
    if (e0 >= E) return;
    const bool has1 = (e1 < E);

    // Row offsets in uint4 units (row = 16 uint4). 32-bit throughout.
    // For int64 indices (< 50000) the low 32-bit word is exact.
    unsigned s0, d0, s1, d1;
    if (g_idx_is64) {
        const unsigned* sp = (const unsigned*)srcp;   // low words of int64
        const unsigned* dp = (const unsigned*)dstp;
        s0 = __ldcs(&sp[2 * e0]); d0 = __ldcs(&dp[2 * e0]);
        s1 = has1 ? __ldcs(&sp[2 * e1]) : s0;
        d1 = has1 ? __ldcs(&dp[2 * e1]) : d0;
    } else {
        const unsigned* sp = (const unsigned*)srcp;
        const unsigned* dp = (const unsigned*)dstp;
        s0 = __ldcs(&sp[e0]); d0 = __ldcs(&dp[e0]);
        s1 = has1 ? __ldcs(&sp[e1]) : s0;
        d1 = has1 ? __ldcs(&dp[e1]) : d0;
    }

    const uint4* __restrict__ base = (const uint4*)g_h16;
    const unsigned o_a0 = s0 * 16u + (unsigned)g;
    const unsigned o_b0 = d0 * 16u + (unsigned)g;
    const unsigned o_a1 = s1 * 16u + (unsigned)g;
    const unsigned o_b1 = d1 * 16u + (unsigned)g;

    // 8 independent loads, all issued before any consumption.
    uint4 a00 = __ldg(base + o_a0);
    uint4 a01 = __ldg(base + o_a0 + 8);
    uint4 b00 = __ldg(base + o_b0);
    uint4 b01 = __ldg(base + o_b0 + 8);
    uint4 a10 = __ldg(base + o_a1);
    uint4 a11 = __ldg(base + o_a1 + 8);
    uint4 b10 = __ldg(base + o_b1);
    uint4 b11 = __ldg(base + o_b1 + 8);

    // fp16 products, one pairwise fp16 add, then fp32 accumulation.
    #define DOT_U4(A, B, ACC)                                              \
    {                                                                      \
        __half2 _dp0 = __hmul2(*(const __half2*)&(A).x,                    \
                               *(const __half2*)&(B).x);                   \
        __half2 _dp1 = __hmul2(*(const __half2*)&(A).y,                    \
                               *(const __half2*)&(B).y);                   \
        __half2 _dp2 = __hmul2(*(const __half2*)&(A).z,                    \
                               *(const __half2*)&(B).z);                   \
        __half2 _dp3 = __hmul2(*(const __half2*)&(A).w,                    \
                               *(const __half2*)&(B).w);                   \
        __half2 _dq0 = __hadd2(_dp0, _dp1);                                \
        __half2 _dq1 = __hadd2(_dp2, _dp3);                                \
        float2 _df0 = __half22float2(_dq0);                                \
        float2 _df1 = __half22float2(_dq1);                                \
        ACC += (_df0.x + _df0.y) + (_df1.x + _df1.y);                      \
    }

    float p0 = 0.f, p1 = 0.f;
    DOT_U4(a00, b00, p0)
    DOT_U4(a01, b01, p0)
    DOT_U4(a10, b10, p1)
    DOT_U4(a11, b11, p1)

    // Combined reduction: xor-4 on both edges, then route p0 -> lanes 0-3,
    // p1 -> lanes 4-7, and finish both with two more shfl steps.
    p0 += __shfl_xor_sync(0xffffffffu, p0, 4);
    p1 += __shfl_xor_sync(0xffffffffu, p1, 4);
    float v = (g < 4) ? p0 : p1;
    v += __shfl_xor_sync(0xffffffffu, v, 2);
    v += __shfl_xor_sync(0xffffffffu, v, 1);

    if (g == 0) __stcs(&out[e0], v);
    if (g == 4 && has1) __stcs(&out[e1], v);
}

extern "C" void kernel_launch(void* const* d_in, const int* in_sizes, int n_in,
                              void* d_out, int out_size) {
    const float* h   = (const float*)d_in[0];
    const void*  src = d_in[1];
    const void*  dst = d_in[2];
    float*       out = (float*)d_out;
    const int E  = in_sizes[1];
    const int n4 = in_sizes[0] / 4;   // N*D/4 float4s

    convert_kernel<<<(n4 + 255) / 256, 256>>>(
        (const float4*)h, n4, (const unsigned*)src);

    const int threads = 256;
    const int npairs  = (E + 1) / 2;                 // groups of 2 edges
    const long long total = (long long)npairs * 8;   // 8 lanes per group
    const int blocks = (int)((total + threads - 1) / threads);
    edge_dot_kernel<<<blocks, threads>>>(src, dst, out, E);
}

// round 12
// speedup vs baseline: 1.3113x; 1.0132x over previous
#include <cuda_runtime.h>
#include <cuda_fp16.h>
#include <stdint.h>

#define N_NODES 50000
#define D_FEAT  128

// fp16 copy of h, rebuilt every kernel_launch (graph-safe, no allocation).
__device__ __half2 g_h16[N_NODES * (D_FEAT / 2)];

// 1 if indices are int64, 0 if int32. Written by convert_kernel block 0.
__device__ int g_idx_is64;

// Convert h (fp32) -> g_h16 (fp16). Block 0 additionally detects the index
// dtype (int64 indices < 50000 have all-zero odd words; int32 does not).
__global__ __launch_bounds__(256) void convert_kernel(
    const float4* __restrict__ h4, int n4,
    const unsigned* __restrict__ src_words)
{
    if (blockIdx.x == 0) {
        __shared__ unsigned red[256];
        unsigned v = 0;
        #pragma unroll 4
        for (int i = threadIdx.x; i < 2048; i += 256)
            v |= __ldcs(&src_words[2 * i + 1]);
        red[threadIdx.x] = v;
        __syncthreads();
        for (int s = 128; s > 0; s >>= 1) {
            if (threadIdx.x < s) red[threadIdx.x] |= red[threadIdx.x + s];
            __syncthreads();
        }
        if (threadIdx.x == 0) g_idx_is64 = (red[0] == 0u) ? 1 : 0;
    }

    int i = blockIdx.x * blockDim.x + threadIdx.x;
    if (i >= n4) return;
    float4 v = __ldcs(&h4[i]);
    __half2 lo = __floats2half2_rn(v.x, v.y);
    __half2 hi = __floats2half2_rn(v.z, v.w);
    ((__half2*)g_h16)[2 * i]     = lo;
    ((__half2*)g_h16)[2 * i + 1] = hi;
}

// 8 lanes per group, TWO edges per group, full-128B-line LDG.128 accesses,
// fp16 product + depth-1 fp16 add, fp32 carry, 32-bit offset addressing,
// occ-8 (32 regs). This round: vectorized index loads — e0,e1 are
// consecutive, so one int2 (int32) / int4 (int64) load per index array
// replaces two scalar loads, cutting per-warp LSU instructions 14 -> 12.
__global__ __launch_bounds__(256, 8) void edge_dot_kernel(
    const void* __restrict__ srcp,
    const void* __restrict__ dstp,
    float*      __restrict__ out,
    int E)
{
    const int gtid = blockIdx.x * blockDim.x + threadIdx.x;
    const int grp  = gtid >> 3;          // group id
    const int g    = threadIdx.x & 7;    // lane within group
    const int e0   = grp * 2;            // even
    const int e1   = e0 + 1;
    if (e0 >= E) return;
    const bool has1 = (e1 < E);

    // Row indices, 32-bit (int64 low word is exact for values < 50000).
    unsigned s0, d0, s1, d1;
    if (g_idx_is64) {
        if (has1) {
            // Two consecutive int64 = one 16B load; .x/.z are low words.
            uint4 sv = __ldcs((const uint4*)((const long long*)srcp + e0));
            uint4 dv = __ldcs((const uint4*)((const long long*)dstp + e0));
            s0 = sv.x; s1 = sv.z;
            d0 = dv.x; d1 = dv.z;
        } else {
            s0 = s1 = __ldcs((const unsigned*)((const long long*)srcp + e0));
            d0 = d1 = __ldcs((const unsigned*)((const long long*)dstp + e0));
        }
    } else {
        if (has1) {
            uint2 sv = __ldcs((const uint2*)((const unsigned*)srcp + e0));
            uint2 dv = __ldcs((const uint2*)((const unsigned*)dstp + e0));
            s0 = sv.x; s1 = sv.y;
            d0 = dv.x; d1 = dv.y;
        } else {
            s0 = s1 = __ldcs((const unsigned*)srcp + e0);
            d0 = d1 = __ldcs((const unsigned*)dstp + e0);
        }
    }

    const uint4* __restrict__ base = (const uint4*)g_h16;
    const unsigned o_a0 = s0 * 16u + (unsigned)g;
    const unsigned o_b0 = d0 * 16u + (unsigned)g;
    const unsigned o_a1 = s1 * 16u + (unsigned)g;
    const unsigned o_b1 = d1 * 16u + (unsigned)g;

    // 8 independent loads, all issued before any consumption.
    uint4 a00 = __ldg(base + o_a0);
    uint4 a01 = __ldg(base + o_a0 + 8);
    uint4 b00 = __ldg(base + o_b0);
    uint4 b01 = __ldg(base + o_b0 + 8);
    uint4 a10 = __ldg(base + o_a1);
    uint4 a11 = __ldg(base + o_a1 + 8);
    uint4 b10 = __ldg(base + o_b1);
    uint4 b11 = __ldg(base + o_b1 + 8);

    // fp16 products, one pairwise fp16 add, then fp32 accumulation.
    #define DOT_U4(A, B, ACC)                                              \
    {                                                                      \
        __half2 _dp0 = __hmul2(*(const __half2*)&(A).x,                    \
                               *(const __half2*)&(B).x);                   \
        __half2 _dp1 = __hmul2(*(const __half2*)&(A).y,                    \
                               *(const __half2*)&(B).y);                   \
        __half2 _dp2 = __hmul2(*(const __half2*)&(A).z,                    \
                               *(const __half2*)&(B).z);                   \
        __half2 _dp3 = __hmul2(*(const __half2*)&(A).w,                    \
                               *(const __half2*)&(B).w);                   \
        __half2 _dq0 = __hadd2(_dp0, _dp1);                                \
        __half2 _dq1 = __hadd2(_dp2, _dp3);                                \
        float2 _df0 = __half22float2(_dq0);                                \
        float2 _df1 = __half22float2(_dq1);                                \
        ACC += (_df0.x + _df0.y) + (_df1.x + _df1.y);                      \
    }

    float p0 = 0.f, p1 = 0.f;
    DOT_U4(a00, b00, p0)
    DOT_U4(a01, b01, p0)
    DOT_U4(a10, b10, p1)
    DOT_U4(a11, b11, p1)

    // Combined reduction: xor-4 on both edges, then route p0 -> lanes 0-3,
    // p1 -> lanes 4-7, and finish both with two more shfl steps.
    p0 += __shfl_xor_sync(0xffffffffu, p0, 4);
    p1 += __shfl_xor_sync(0xffffffffu, p1, 4);
    float v = (g < 4) ? p0 : p1;
    v += __shfl_xor_sync(0xffffffffu, v, 2);
    v += __shfl_xor_sync(0xffffffffu, v, 1);

    if (g == 0) __stcs(&out[e0], v);
    if (g == 4 && has1) __stcs(&out[e1], v);
}

extern "C" void kernel_launch(void* const* d_in, const int* in_sizes, int n_in,
                              void* d_out, int out_size) {
    const float* h   = (const float*)d_in[0];
    const void*  src = d_in[1];
    const void*  dst = d_in[2];
    float*       out = (float*)d_out;
    const int E  = in_sizes[1];
    const int n4 = in_sizes[0] / 4;   // N*D/4 float4s

    convert_kernel<<<(n4 + 255) / 256, 256>>>(
        (const float4*)h, n4, (const unsigned*)src);

    const int threads = 256;
    const int npairs  = (E + 1) / 2;                 // groups of 2 edges
    const long long total = (long long)npairs * 8;   // 8 lanes per group
    const int blocks = (int)((total + threads - 1) / threads);
    edge_dot_kernel<<<blocks, threads>>>(src, dst, out, E);
}